// round 1
// baseline (speedup 1.0000x reference)
#include <cuda_runtime.h>
#include <math.h>

#define B_ 2
#define T_ 2048
#define C_ 1024
#define H_ 16
#define D_ 64
#define M_ (B_*T_)          // 4096 rows in projection GEMMs
#define NELEM (B_*T_*C_)    // 4,194,304 per activation tensor

// Scratch (device globals: allocation-free rule)
__device__ float g_q[NELEM];
__device__ float g_k[NELEM];
__device__ float g_v[NELEM];
__device__ float g_att[NELEM];

// ---------------------------------------------------------------------------
// SGEMM: out[M,N] = A[M,K] @ W[N,K]^T + bias[N]
// 128x128 block tile, BK=16, 256 threads, 8x8 per-thread register tile.
// ---------------------------------------------------------------------------
#define BM 128
#define BN 128
#define BK 16

__device__ __forceinline__ void sgemm128(
    const float* __restrict__ A, const float* __restrict__ W,
    const float* __restrict__ bias, float* __restrict__ out,
    int M, int N, int K)
{
    __shared__ float As[BK][BM];   // As[k][m]
    __shared__ float Ws[BK][BN];   // Ws[k][n]

    const int tid = threadIdx.x;
    const int m0 = blockIdx.y * BM;
    const int n0 = blockIdx.x * BN;
    const int tx = tid & 15;
    const int ty = tid >> 4;

    const int lr = tid >> 2;          // 0..63
    const int lc = (tid & 3) * 4;     // 0,4,8,12

    float acc[8][8];
    #pragma unroll
    for (int i = 0; i < 8; i++)
        #pragma unroll
        for (int j = 0; j < 8; j++) acc[i][j] = 0.f;

    for (int k0 = 0; k0 < K; k0 += BK) {
        #pragma unroll
        for (int h = 0; h < 2; h++) {
            int r = lr + h * 64;
            float4 a = *(const float4*)(A + (size_t)(m0 + r) * K + k0 + lc);
            As[lc + 0][r] = a.x; As[lc + 1][r] = a.y;
            As[lc + 2][r] = a.z; As[lc + 3][r] = a.w;
            float4 w = *(const float4*)(W + (size_t)(n0 + r) * K + k0 + lc);
            Ws[lc + 0][r] = w.x; Ws[lc + 1][r] = w.y;
            Ws[lc + 2][r] = w.z; Ws[lc + 3][r] = w.w;
        }
        __syncthreads();

        #pragma unroll
        for (int kk = 0; kk < BK; kk++) {
            float af[8], wf[8];
            *(float4*)(af)     = *(const float4*)&As[kk][ty * 8];
            *(float4*)(af + 4) = *(const float4*)&As[kk][ty * 8 + 4];
            *(float4*)(wf)     = *(const float4*)&Ws[kk][tx * 8];
            *(float4*)(wf + 4) = *(const float4*)&Ws[kk][tx * 8 + 4];
            #pragma unroll
            for (int i = 0; i < 8; i++)
                #pragma unroll
                for (int j = 0; j < 8; j++)
                    acc[i][j] += af[i] * wf[j];
        }
        __syncthreads();
    }

    #pragma unroll
    for (int i = 0; i < 8; i++) {
        int m = m0 + ty * 8 + i;
        #pragma unroll
        for (int j = 0; j < 8; j += 4) {
            int n = n0 + tx * 8 + j;
            float4 b4 = *(const float4*)(bias + n);
            float4 o4;
            o4.x = acc[i][j + 0] + b4.x;
            o4.y = acc[i][j + 1] + b4.y;
            o4.z = acc[i][j + 2] + b4.z;
            o4.w = acc[i][j + 3] + b4.w;
            *(float4*)(out + (size_t)m * N + n) = o4;
        }
    }
}

__global__ void __launch_bounds__(256) qkv_kernel(
    const float* __restrict__ x,
    const float* __restrict__ wq, const float* __restrict__ bq,
    const float* __restrict__ wk, const float* __restrict__ bk,
    const float* __restrict__ wv, const float* __restrict__ bv)
{
    const float* W; const float* bias; float* out;
    if (blockIdx.z == 0)      { W = wq; bias = bq; out = g_q; }
    else if (blockIdx.z == 1) { W = wk; bias = bk; out = g_k; }
    else                      { W = wv; bias = bv; out = g_v; }
    sgemm128(x, W, bias, out, M_, C_, C_);
}

__global__ void __launch_bounds__(256) oproj_kernel(
    const float* __restrict__ wo, const float* __restrict__ bo,
    float* __restrict__ out)
{
    sgemm128(g_att, wo, bo, out, M_, C_, C_);
}

// ---------------------------------------------------------------------------
// RoPE (in-place on g_q, g_k).
// out[2i]   = x[2i]  *cos(a(2i))   - x[2i+1]*sin(a(2i))
// out[2i+1] = x[2i+1]*cos(a(2i+1)) + x[2i]  *sin(a(2i+1))
// a(d) = t * 10000^(-(d mod 32)/32), inv_freq matched to fp32 JAX table.
// ---------------------------------------------------------------------------
__global__ void __launch_bounds__(256) rope_kernel()
{
    __shared__ float invf[32];
    if (threadIdx.x < 32) {
        // ln(10000)/32 in double; correctly-rounded fp32 result matches JAX table
        invf[threadIdx.x] =
            (float)exp(-(double)threadIdx.x * 0.28782313662425560116456546736598);
    }
    __syncthreads();

    int idx = blockIdx.x * blockDim.x + threadIdx.x;
    if (idx >= B_ * T_ * (C_ / 2)) return;
    int p  = idx & (C_ / 2 - 1);      // pair index within row, 0..511
    int bt = idx >> 9;
    int t  = bt & (T_ - 1);
    int c  = p * 2;
    int d0 = c & (D_ - 1);            // even, 0..62 within head

    float a0 = (float)t * invf[d0 & 31];
    float a1 = (float)t * invf[(d0 + 1) & 31];
    float s0, c0, s1, c1;
    sincosf(a0, &s0, &c0);
    sincosf(a1, &s1, &c1);

    size_t off = (size_t)bt * C_ + c;
    float2 q = *(float2*)(g_q + off);
    float2 k = *(float2*)(g_k + off);
    *(float2*)(g_q + off) = make_float2(q.x * c0 - q.y * s0, q.y * c1 + q.x * s1);
    *(float2*)(g_k + off) = make_float2(k.x * c0 - k.y * s0, k.y * c1 + k.x * s1);
}

// ---------------------------------------------------------------------------
// Flash attention: one block = 64 q-rows of one (b,h). 128 threads.
// Thread (ty=tid/16, tx=tid%16) owns rows ty*8+i (i<8), cols tx*4+j (j<4).
// Smem: Qst[d][r], Kt[d][kr] (d-major -> broadcast/conflict-free LDS),
//       Vs[kr][d], Ps[r][kc]. 4 * 16KB = 64KB dynamic smem.
// ---------------------------------------------------------------------------
__global__ void __launch_bounds__(128) flash_kernel()
{
    extern __shared__ float sm[];
    float* Qst = sm;                 // [64][64] Qst[d][r]
    float* Kt  = sm + 64 * 64;       // [64][64] Kt[d][kr]
    float* Vs  = sm + 2 * 64 * 64;   // [64][64] Vs[kr][d]
    float* Ps  = sm + 3 * 64 * 64;   // [64][64] Ps[r][kc]

    const int tid = threadIdx.x;
    const int b = blockIdx.y >> 4;
    const int h = blockIdx.y & 15;
    const int t0 = blockIdx.x * 64;
    const int tx = tid & 15;
    const int ty = tid >> 4;

    const size_t rowbase = (size_t)(b * T_) * C_ + h * D_;

    // Load Q tile transposed, pre-scaled by 1/sqrt(D)=0.125
    #pragma unroll
    for (int it = 0; it < 8; it++) {
        int f4 = it * 128 + tid;
        int r  = f4 >> 4;
        int c4 = (f4 & 15) * 4;
        float4 q = *(const float4*)(g_q + rowbase + (size_t)(t0 + r) * C_ + c4);
        Qst[(c4 + 0) * 64 + r] = q.x * 0.125f;
        Qst[(c4 + 1) * 64 + r] = q.y * 0.125f;
        Qst[(c4 + 2) * 64 + r] = q.z * 0.125f;
        Qst[(c4 + 3) * 64 + r] = q.w * 0.125f;
    }

    float m_r[8], l_r[8], o[8][4];
    #pragma unroll
    for (int i = 0; i < 8; i++) {
        m_r[i] = -INFINITY; l_r[i] = 0.f;
        #pragma unroll
        for (int j = 0; j < 4; j++) o[i][j] = 0.f;
    }

    for (int kt = 0; kt < T_ / 64; kt++) {
        __syncthreads();  // prior PV readers done; Qst visible on first iter

        #pragma unroll
        for (int it = 0; it < 8; it++) {
            int f4 = it * 128 + tid;
            int r  = f4 >> 4;
            int c4 = (f4 & 15) * 4;
            size_t g = rowbase + (size_t)(kt * 64 + r) * C_ + c4;
            float4 kk4 = *(const float4*)(g_k + g);
            Kt[(c4 + 0) * 64 + r] = kk4.x;
            Kt[(c4 + 1) * 64 + r] = kk4.y;
            Kt[(c4 + 2) * 64 + r] = kk4.z;
            Kt[(c4 + 3) * 64 + r] = kk4.w;
            *(float4*)(Vs + r * 64 + c4) = *(const float4*)(g_v + g);
        }
        __syncthreads();

        // S = (Q/8) @ K^T  (64x64), register tile 8x4
        float s[8][4];
        #pragma unroll
        for (int i = 0; i < 8; i++)
            #pragma unroll
            for (int j = 0; j < 4; j++) s[i][j] = 0.f;

        #pragma unroll 8
        for (int kk = 0; kk < 64; kk++) {
            float4 a0 = *(const float4*)(Qst + kk * 64 + ty * 8);
            float4 a1 = *(const float4*)(Qst + kk * 64 + ty * 8 + 4);
            float4 bv = *(const float4*)(Kt + kk * 64 + tx * 4);
            float af[8] = {a0.x, a0.y, a0.z, a0.w, a1.x, a1.y, a1.z, a1.w};
            float bf[4] = {bv.x, bv.y, bv.z, bv.w};
            #pragma unroll
            for (int i = 0; i < 8; i++)
                #pragma unroll
                for (int j = 0; j < 4; j++)
                    s[i][j] += af[i] * bf[j];
        }

        // Online softmax (row reduction across the 16 tx lanes)
        #pragma unroll
        for (int i = 0; i < 8; i++) {
            float mx = fmaxf(fmaxf(s[i][0], s[i][1]), fmaxf(s[i][2], s[i][3]));
            #pragma unroll
            for (int off = 8; off >= 1; off >>= 1)
                mx = fmaxf(mx, __shfl_xor_sync(0xffffffffu, mx, off));
            float mn = fmaxf(m_r[i], mx);
            float sc = __expf(m_r[i] - mn);
            l_r[i] *= sc;
            #pragma unroll
            for (int j = 0; j < 4; j++) o[i][j] *= sc;
            float rs = 0.f;
            #pragma unroll
            for (int j = 0; j < 4; j++) {
                float pv = __expf(s[i][j] - mn);
                s[i][j] = pv;
                rs += pv;
            }
            #pragma unroll
            for (int off = 8; off >= 1; off >>= 1)
                rs += __shfl_xor_sync(0xffffffffu, rs, off);
            l_r[i] += rs;
            m_r[i] = mn;
            *(float4*)(Ps + (ty * 8 + i) * 64 + tx * 4) =
                make_float4(s[i][0], s[i][1], s[i][2], s[i][3]);
        }
        __syncthreads();

        // O += P @ V
        #pragma unroll 8
        for (int kk = 0; kk < 64; kk++) {
            float4 v4 = *(const float4*)(Vs + kk * 64 + tx * 4);
            #pragma unroll
            for (int i = 0; i < 8; i++) {
                float pv = Ps[(ty * 8 + i) * 64 + kk];
                o[i][0] += pv * v4.x;
                o[i][1] += pv * v4.y;
                o[i][2] += pv * v4.z;
                o[i][3] += pv * v4.w;
            }
        }
    }

    // Normalize and write out in [B,T,C] layout
    #pragma unroll
    for (int i = 0; i < 8; i++) {
        float inv = 1.0f / l_r[i];
        float4 o4 = make_float4(o[i][0] * inv, o[i][1] * inv,
                                o[i][2] * inv, o[i][3] * inv);
        *(float4*)(g_att + rowbase + (size_t)(t0 + ty * 8 + i) * C_ + tx * 4) = o4;
    }
}

// ---------------------------------------------------------------------------
extern "C" void kernel_launch(void* const* d_in, const int* in_sizes, int n_in,
                              void* d_out, int out_size)
{
    const float* x  = (const float*)d_in[0];
    const float* wq = (const float*)d_in[1];
    const float* bq = (const float*)d_in[2];
    const float* wk = (const float*)d_in[3];
    const float* bk = (const float*)d_in[4];
    const float* wv = (const float*)d_in[5];
    const float* bv = (const float*)d_in[6];
    const float* wo = (const float*)d_in[7];
    const float* bo = (const float*)d_in[8];
    float* out = (float*)d_out;

    // QKV projections
    dim3 gqkv(C_ / BN, M_ / BM, 3);   // (8, 32, 3)
    qkv_kernel<<<gqkv, 256>>>(x, wq, bq, wk, bk, wv, bv);

    // RoPE on Q and K
    int npairs = B_ * T_ * (C_ / 2);  // 2,097,152
    rope_kernel<<<(npairs + 255) / 256, 256>>>();

    // Flash attention
    cudaFuncSetAttribute(flash_kernel,
                         cudaFuncAttributeMaxDynamicSharedMemorySize, 65536);
    flash_kernel<<<dim3(T_ / 64, B_ * H_), 128, 65536>>>();

    // Output projection
    oproj_kernel<<<dim3(C_ / BN, M_ / BM), 256>>>(wo, bo, out);
}

// round 4
// speedup vs baseline: 1.3686x; 1.3686x over previous
#include <cuda_runtime.h>
#include <cuda_bf16.h>
#include <cstdint>
#include <math.h>

#define B_ 2
#define T_ 2048
#define C_ 1024
#define H_ 16
#define D_ 64
#define M_ (B_*T_)
#define NELEM (B_*T_*C_)
#define KDIM 1024

// Scratch (device globals: allocation-free rule)
__device__ float g_q[NELEM];
__device__ float g_k[NELEM];
__device__ float g_v[NELEM];
__device__ __nv_bfloat16 g_xh[NELEM];
__device__ __nv_bfloat16 g_xl[NELEM];
__device__ __nv_bfloat16 g_wh[4 * C_ * C_];
__device__ __nv_bfloat16 g_wl[4 * C_ * C_];
__device__ __nv_bfloat16 g_ah[NELEM];
__device__ __nv_bfloat16 g_al[NELEM];

// ---------------------------------------------------------------------------
// fp32 -> (bf16 hi, bf16 lo) split, vectorized by 4
// ---------------------------------------------------------------------------
__global__ void __launch_bounds__(256) split_kernel(
    const float* __restrict__ src, __nv_bfloat16* __restrict__ hi,
    __nv_bfloat16* __restrict__ lo, int n4)
{
    int i = blockIdx.x * blockDim.x + threadIdx.x;
    if (i >= n4) return;
    float4 v = ((const float4*)src)[i];
    float vv[4] = {v.x, v.y, v.z, v.w};
    __nv_bfloat16 h[4], l[4];
    #pragma unroll
    for (int j = 0; j < 4; j++) {
        h[j] = __float2bfloat16_rn(vv[j]);
        l[j] = __float2bfloat16_rn(vv[j] - __bfloat162float(h[j]));
    }
    *(__nv_bfloat162*)(hi + 4 * i)     = __halves2bfloat162(h[0], h[1]);
    *(__nv_bfloat162*)(hi + 4 * i + 2) = __halves2bfloat162(h[2], h[3]);
    *(__nv_bfloat162*)(lo + 4 * i)     = __halves2bfloat162(l[0], l[1]);
    *(__nv_bfloat162*)(lo + 4 * i + 2) = __halves2bfloat162(l[2], l[3]);
}

// ---------------------------------------------------------------------------
// bf16 3-term GEMM: out[M,1024] = (Ah+Al)[M,K] @ (Bh+Bl)[1024,K]^T + bias
// (terms AhBh + AhBl + AlBh).  Block 128x128, BK=32, 256 threads (8 warps),
// warp tile 32x64 via mma.sync.m16n8k16.  cp.async double buffer.
// Smem row pitch 40 bf16 (80B): conflict-free ldmatrix.
// ---------------------------------------------------------------------------
#define SM_STAGE_BYTES 40960   // (A:256 rows + B:256 rows) * 80B
#define SM_B_OFF 20480

#define CP16(dst, src) \
    asm volatile("cp.async.ca.shared.global [%0], [%1], 16;" :: "r"(dst), "l"(src))

#define LDSM4(r, addr) \
    asm volatile("ldmatrix.sync.aligned.m8n8.x4.shared.b16 {%0,%1,%2,%3}, [%4];" \
        : "=r"(r[0]), "=r"(r[1]), "=r"(r[2]), "=r"(r[3]) : "r"(addr))

#define MMA16816(d, a, b) \
    asm volatile("mma.sync.aligned.m16n8k16.row.col.f32.bf16.bf16.f32 " \
        "{%0,%1,%2,%3}, {%4,%5,%6,%7}, {%8,%9}, {%0,%1,%2,%3};" \
        : "+f"(d[0]), "+f"(d[1]), "+f"(d[2]), "+f"(d[3]) \
        : "r"(a[0]), "r"(a[1]), "r"(a[2]), "r"(a[3]), "r"(b[0]), "r"(b[1]))

__device__ __forceinline__ void stage_load(
    unsigned sdst,
    const __nv_bfloat16* __restrict__ Ah, const __nv_bfloat16* __restrict__ Al,
    const __nv_bfloat16* __restrict__ Bh, const __nv_bfloat16* __restrict__ Bl,
    int m0, int n0, int k0, int r0, int q)
{
    const __nv_bfloat16* a = Ah + (size_t)(m0 + r0) * KDIM + k0 + q * 8;
    CP16(sdst + r0 * 80 + q * 16, a);
    CP16(sdst + (r0 + 64) * 80 + q * 16, a + 64 * KDIM);
    const __nv_bfloat16* a2 = Al + (size_t)(m0 + r0) * KDIM + k0 + q * 8;
    CP16(sdst + (r0 + 128) * 80 + q * 16, a2);
    CP16(sdst + (r0 + 192) * 80 + q * 16, a2 + 64 * KDIM);

    unsigned bdst = sdst + SM_B_OFF;
    const __nv_bfloat16* b = Bh + (size_t)(n0 + r0) * KDIM + k0 + q * 8;
    CP16(bdst + r0 * 80 + q * 16, b);
    CP16(bdst + (r0 + 64) * 80 + q * 16, b + 64 * KDIM);
    const __nv_bfloat16* b2 = Bl + (size_t)(n0 + r0) * KDIM + k0 + q * 8;
    CP16(bdst + (r0 + 128) * 80 + q * 16, b2);
    CP16(bdst + (r0 + 192) * 80 + q * 16, b2 + 64 * KDIM);
}

__device__ __forceinline__ void bf16gemm3(
    const __nv_bfloat16* __restrict__ Ah, const __nv_bfloat16* __restrict__ Al,
    const __nv_bfloat16* __restrict__ Bh, const __nv_bfloat16* __restrict__ Bl,
    const float* __restrict__ bias, float* __restrict__ out)
{
    extern __shared__ __nv_bfloat16 smem[];
    const int tid = threadIdx.x;
    const int lane = tid & 31;
    const int wid = tid >> 5;
    const int warp_m = wid & 3;
    const int warp_n = wid >> 2;
    const int m0 = blockIdx.y * 128;
    const int n0 = blockIdx.x * 128;
    const int q = tid & 3;
    const int r0 = tid >> 2;

    unsigned sbase = (unsigned)__cvta_generic_to_shared(smem);

    float acc[2][8][4];
    #pragma unroll
    for (int mt = 0; mt < 2; mt++)
        #pragma unroll
        for (int nt = 0; nt < 8; nt++)
            #pragma unroll
            for (int j = 0; j < 4; j++) acc[mt][nt][j] = 0.f;

    stage_load(sbase, Ah, Al, Bh, Bl, m0, n0, 0, r0, q);
    asm volatile("cp.async.commit_group;");

    for (int kt = 0; kt < 32; kt++) {
        if (kt < 31)
            stage_load(sbase + ((kt + 1) & 1) * SM_STAGE_BYTES,
                       Ah, Al, Bh, Bl, m0, n0, (kt + 1) * 32, r0, q);
        asm volatile("cp.async.commit_group;");
        asm volatile("cp.async.wait_group 1;");
        __syncthreads();

        unsigned base = sbase + (kt & 1) * SM_STAGE_BYTES;
        #pragma unroll
        for (int ks = 0; ks < 2; ks++) {
            unsigned lofs = (lane & 15) * 80 + (lane >> 4) * 16 + ks * 32;
            uint32_t ah[2][4], al[2][4];
            #pragma unroll
            for (int mt = 0; mt < 2; mt++) {
                unsigned ra = (warp_m * 32 + mt * 16);
                LDSM4(ah[mt], base + ra * 80 + lofs);
                LDSM4(al[mt], base + (ra + 128) * 80 + lofs);
            }
            uint32_t bh[8][2], bl[8][2];
            #pragma unroll
            for (int np = 0; np < 4; np++) {
                unsigned rb = (warp_n * 64 + np * 16);
                uint32_t t[4];
                LDSM4(t, base + SM_B_OFF + rb * 80 + lofs);
                bh[2 * np][0] = t[0]; bh[2 * np][1] = t[2];
                bh[2 * np + 1][0] = t[1]; bh[2 * np + 1][1] = t[3];
                LDSM4(t, base + SM_B_OFF + (rb + 128) * 80 + lofs);
                bl[2 * np][0] = t[0]; bl[2 * np][1] = t[2];
                bl[2 * np + 1][0] = t[1]; bl[2 * np + 1][1] = t[3];
            }
            #pragma unroll
            for (int mt = 0; mt < 2; mt++)
                #pragma unroll
                for (int nt = 0; nt < 8; nt++) {
                    MMA16816(acc[mt][nt], ah[mt], bh[nt]);
                    MMA16816(acc[mt][nt], ah[mt], bl[nt]);
                    MMA16816(acc[mt][nt], al[mt], bh[nt]);
                }
        }
        __syncthreads();
    }

    #pragma unroll
    for (int mt = 0; mt < 2; mt++) {
        int m = m0 + warp_m * 32 + mt * 16 + (lane >> 2);
        #pragma unroll
        for (int nt = 0; nt < 8; nt++) {
            int n = n0 + warp_n * 64 + nt * 8 + 2 * (lane & 3);
            float2 b2 = *(const float2*)(bias + n);
            float2 v0 = make_float2(acc[mt][nt][0] + b2.x, acc[mt][nt][1] + b2.y);
            float2 v1 = make_float2(acc[mt][nt][2] + b2.x, acc[mt][nt][3] + b2.y);
            *(float2*)(out + (size_t)m * C_ + n) = v0;
            *(float2*)(out + (size_t)(m + 8) * C_ + n) = v1;
        }
    }
}

__global__ void __launch_bounds__(256) qkv_kernel(
    const float* __restrict__ bq, const float* __restrict__ bk,
    const float* __restrict__ bv)
{
    int z = blockIdx.z;
    const float* bias = (z == 0) ? bq : (z == 1) ? bk : bv;
    float* out = (z == 0) ? g_q : (z == 1) ? g_k : g_v;
    bf16gemm3(g_xh, g_xl, g_wh + (size_t)z * C_ * C_, g_wl + (size_t)z * C_ * C_,
              bias, out);
}

__global__ void __launch_bounds__(256) oproj_kernel(
    const float* __restrict__ bo, float* __restrict__ out)
{
    bf16gemm3(g_ah, g_al, g_wh + (size_t)3 * C_ * C_, g_wl + (size_t)3 * C_ * C_,
              bo, out);
}

// ---------------------------------------------------------------------------
// RoPE (in-place on g_q, g_k)
// ---------------------------------------------------------------------------
__global__ void __launch_bounds__(256) rope_kernel()
{
    __shared__ float invf[32];
    if (threadIdx.x < 32) {
        invf[threadIdx.x] =
            (float)exp(-(double)threadIdx.x * 0.28782313662425560116456546736598);
    }
    __syncthreads();

    int idx = blockIdx.x * blockDim.x + threadIdx.x;
    if (idx >= B_ * T_ * (C_ / 2)) return;
    int p  = idx & (C_ / 2 - 1);
    int bt = idx >> 9;
    int t  = bt & (T_ - 1);
    int c  = p * 2;
    int d0 = c & (D_ - 1);

    float a0 = (float)t * invf[d0 & 31];
    float a1 = (float)t * invf[(d0 + 1) & 31];
    float s0, c0, s1, c1;
    sincosf(a0, &s0, &c0);
    sincosf(a1, &s1, &c1);

    size_t off = (size_t)bt * C_ + c;
    float2 qv = *(float2*)(g_q + off);
    float2 kv = *(float2*)(g_k + off);
    *(float2*)(g_q + off) = make_float2(qv.x * c0 - qv.y * s0, qv.y * c1 + qv.x * s1);
    *(float2*)(g_k + off) = make_float2(kv.x * c0 - kv.y * s0, kv.y * c1 + kv.x * s1);
}

// ---------------------------------------------------------------------------
// Flash attention (fp32 FFMA), epilogue writes bf16 hi/lo for oproj
// ---------------------------------------------------------------------------
__global__ void __launch_bounds__(128) flash_kernel()
{
    extern __shared__ float sm[];
    float* Qst = sm;
    float* Kt  = sm + 64 * 64;
    float* Vs  = sm + 2 * 64 * 64;
    float* Ps  = sm + 3 * 64 * 64;

    const int tid = threadIdx.x;
    const int b = blockIdx.y >> 4;
    const int h = blockIdx.y & 15;
    const int t0 = blockIdx.x * 64;
    const int tx = tid & 15;
    const int ty = tid >> 4;

    const size_t rowbase = (size_t)(b * T_) * C_ + h * D_;

    #pragma unroll
    for (int it = 0; it < 8; it++) {
        int f4 = it * 128 + tid;
        int r  = f4 >> 4;
        int c4 = (f4 & 15) * 4;
        float4 qv = *(const float4*)(g_q + rowbase + (size_t)(t0 + r) * C_ + c4);
        Qst[(c4 + 0) * 64 + r] = qv.x * 0.125f;
        Qst[(c4 + 1) * 64 + r] = qv.y * 0.125f;
        Qst[(c4 + 2) * 64 + r] = qv.z * 0.125f;
        Qst[(c4 + 3) * 64 + r] = qv.w * 0.125f;
    }

    float m_r[8], l_r[8], o[8][4];
    #pragma unroll
    for (int i = 0; i < 8; i++) {
        m_r[i] = -INFINITY; l_r[i] = 0.f;
        #pragma unroll
        for (int j = 0; j < 4; j++) o[i][j] = 0.f;
    }

    for (int kt = 0; kt < T_ / 64; kt++) {
        __syncthreads();

        #pragma unroll
        for (int it = 0; it < 8; it++) {
            int f4 = it * 128 + tid;
            int r  = f4 >> 4;
            int c4 = (f4 & 15) * 4;
            size_t g = rowbase + (size_t)(kt * 64 + r) * C_ + c4;
            float4 kk4 = *(const float4*)(g_k + g);
            Kt[(c4 + 0) * 64 + r] = kk4.x;
            Kt[(c4 + 1) * 64 + r] = kk4.y;
            Kt[(c4 + 2) * 64 + r] = kk4.z;
            Kt[(c4 + 3) * 64 + r] = kk4.w;
            *(float4*)(Vs + r * 64 + c4) = *(const float4*)(g_v + g);
        }
        __syncthreads();

        float s[8][4];
        #pragma unroll
        for (int i = 0; i < 8; i++)
            #pragma unroll
            for (int j = 0; j < 4; j++) s[i][j] = 0.f;

        #pragma unroll 8
        for (int kk = 0; kk < 64; kk++) {
            float4 a0 = *(const float4*)(Qst + kk * 64 + ty * 8);
            float4 a1 = *(const float4*)(Qst + kk * 64 + ty * 8 + 4);
            float4 bv = *(const float4*)(Kt + kk * 64 + tx * 4);
            float af[8] = {a0.x, a0.y, a0.z, a0.w, a1.x, a1.y, a1.z, a1.w};
            float bf[4] = {bv.x, bv.y, bv.z, bv.w};
            #pragma unroll
            for (int i = 0; i < 8; i++)
                #pragma unroll
                for (int j = 0; j < 4; j++)
                    s[i][j] += af[i] * bf[j];
        }

        #pragma unroll
        for (int i = 0; i < 8; i++) {
            float mx = fmaxf(fmaxf(s[i][0], s[i][1]), fmaxf(s[i][2], s[i][3]));
            #pragma unroll
            for (int off = 8; off >= 1; off >>= 1)
                mx = fmaxf(mx, __shfl_xor_sync(0xffffffffu, mx, off));
            float mn = fmaxf(m_r[i], mx);
            float sc = __expf(m_r[i] - mn);
            l_r[i] *= sc;
            #pragma unroll
            for (int j = 0; j < 4; j++) o[i][j] *= sc;
            float rs = 0.f;
            #pragma unroll
            for (int j = 0; j < 4; j++) {
                float pv = __expf(s[i][j] - mn);
                s[i][j] = pv;
                rs += pv;
            }
            #pragma unroll
            for (int off = 8; off >= 1; off >>= 1)
                rs += __shfl_xor_sync(0xffffffffu, rs, off);
            l_r[i] += rs;
            m_r[i] = mn;
            *(float4*)(Ps + (ty * 8 + i) * 64 + tx * 4) =
                make_float4(s[i][0], s[i][1], s[i][2], s[i][3]);
        }
        __syncthreads();

        #pragma unroll 8
        for (int kk = 0; kk < 64; kk++) {
            float4 v4 = *(const float4*)(Vs + kk * 64 + tx * 4);
            #pragma unroll
            for (int i = 0; i < 8; i++) {
                float pv = Ps[(ty * 8 + i) * 64 + kk];
                o[i][0] += pv * v4.x;
                o[i][1] += pv * v4.y;
                o[i][2] += pv * v4.z;
                o[i][3] += pv * v4.w;
            }
        }
    }

    #pragma unroll
    for (int i = 0; i < 8; i++) {
        float inv = 1.0f / l_r[i];
        float vv[4] = {o[i][0] * inv, o[i][1] * inv, o[i][2] * inv, o[i][3] * inv};
        __nv_bfloat16 hh[4], ll[4];
        #pragma unroll
        for (int j = 0; j < 4; j++) {
            hh[j] = __float2bfloat16_rn(vv[j]);
            ll[j] = __float2bfloat16_rn(vv[j] - __bfloat162float(hh[j]));
        }
        size_t off = rowbase + (size_t)(t0 + ty * 8 + i) * C_ + tx * 4;
        *(__nv_bfloat162*)(g_ah + off)     = __halves2bfloat162(hh[0], hh[1]);
        *(__nv_bfloat162*)(g_ah + off + 2) = __halves2bfloat162(hh[2], hh[3]);
        *(__nv_bfloat162*)(g_al + off)     = __halves2bfloat162(ll[0], ll[1]);
        *(__nv_bfloat162*)(g_al + off + 2) = __halves2bfloat162(ll[2], ll[3]);
    }
}

// ---------------------------------------------------------------------------
extern "C" void kernel_launch(void* const* d_in, const int* in_sizes, int n_in,
                              void* d_out, int out_size)
{
    const float* x  = (const float*)d_in[0];
    const float* wq = (const float*)d_in[1];
    const float* bq = (const float*)d_in[2];
    const float* wk = (const float*)d_in[3];
    const float* bk = (const float*)d_in[4];
    const float* wv = (const float*)d_in[5];
    const float* bv = (const float*)d_in[6];
    const float* wo = (const float*)d_in[7];
    const float* bo = (const float*)d_in[8];
    float* out = (float*)d_out;

    __nv_bfloat16 *xh, *xl, *wh, *wl;
    cudaGetSymbolAddress((void**)&xh, g_xh);
    cudaGetSymbolAddress((void**)&xl, g_xl);
    cudaGetSymbolAddress((void**)&wh, g_wh);
    cudaGetSymbolAddress((void**)&wl, g_wl);

    // Split x and weights into bf16 hi/lo
    split_kernel<<<(NELEM / 4 + 255) / 256, 256>>>(x, xh, xl, NELEM / 4);
    int wn4 = C_ * C_ / 4;
    split_kernel<<<(wn4 + 255) / 256, 256>>>(wq, wh + 0 * C_ * C_, wl + 0 * C_ * C_, wn4);
    split_kernel<<<(wn4 + 255) / 256, 256>>>(wk, wh + 1 * C_ * C_, wl + 1 * C_ * C_, wn4);
    split_kernel<<<(wn4 + 255) / 256, 256>>>(wv, wh + 2 * C_ * C_, wl + 2 * C_ * C_, wn4);
    split_kernel<<<(wn4 + 255) / 256, 256>>>(wo, wh + 3 * C_ * C_, wl + 3 * C_ * C_, wn4);

    // QKV projections (bf16x3 tensor core)
    cudaFuncSetAttribute(qkv_kernel,
                         cudaFuncAttributeMaxDynamicSharedMemorySize, 2 * SM_STAGE_BYTES);
    cudaFuncSetAttribute(oproj_kernel,
                         cudaFuncAttributeMaxDynamicSharedMemorySize, 2 * SM_STAGE_BYTES);
    qkv_kernel<<<dim3(C_ / 128, M_ / 128, 3), 256, 2 * SM_STAGE_BYTES>>>(bq, bk, bv);

    // RoPE
    int npairs = B_ * T_ * (C_ / 2);
    rope_kernel<<<(npairs + 255) / 256, 256>>>();

    // Flash attention
    cudaFuncSetAttribute(flash_kernel,
                         cudaFuncAttributeMaxDynamicSharedMemorySize, 65536);
    flash_kernel<<<dim3(T_ / 64, B_ * H_), 128, 65536>>>();

    // Output projection
    oproj_kernel<<<dim3(C_ / 128, M_ / 128), 256, 2 * SM_STAGE_BYTES>>>(bo, out);
}

// round 5
// speedup vs baseline: 2.6432x; 1.9313x over previous
#include <cuda_runtime.h>
#include <cuda_bf16.h>
#include <cstdint>
#include <math.h>

#define B_ 2
#define T_ 2048
#define C_ 1024
#define H_ 16
#define D_ 64
#define M_ (B_*T_)
#define NELEM (B_*T_*C_)
#define KDIM 1024

// Scratch (device globals: allocation-free rule)
__device__ float g_q[NELEM];
__device__ float g_k[NELEM];
__device__ float g_v[NELEM];
__device__ __nv_bfloat16 g_xh[NELEM];
__device__ __nv_bfloat16 g_xl[NELEM];
__device__ __nv_bfloat16 g_wh[4 * C_ * C_];
__device__ __nv_bfloat16 g_wl[4 * C_ * C_];
__device__ __nv_bfloat16 g_ah[NELEM];
__device__ __nv_bfloat16 g_al[NELEM];
// flash operands (bf16 hi/lo)
__device__ __nv_bfloat16 g_qh[NELEM];   // rope'd Q * 0.125*log2e, [b][t][h*64+d]
__device__ __nv_bfloat16 g_ql[NELEM];
__device__ __nv_bfloat16 g_kh[NELEM];   // rope'd K, [b][t][h*64+d]
__device__ __nv_bfloat16 g_kl[NELEM];
__device__ __nv_bfloat16 g_vth[NELEM];  // V transposed: [(b*16+h)*64+d][t]
__device__ __nv_bfloat16 g_vtl[NELEM];

// ---------------------------------------------------------------------------
// fp32 -> (bf16 hi, bf16 lo) split, vectorized by 4
// ---------------------------------------------------------------------------
__global__ void __launch_bounds__(256) split_kernel(
    const float* __restrict__ src, __nv_bfloat16* __restrict__ hi,
    __nv_bfloat16* __restrict__ lo, int n4)
{
    int i = blockIdx.x * blockDim.x + threadIdx.x;
    if (i >= n4) return;
    float4 v = ((const float4*)src)[i];
    float vv[4] = {v.x, v.y, v.z, v.w};
    __nv_bfloat16 h[4], l[4];
    #pragma unroll
    for (int j = 0; j < 4; j++) {
        h[j] = __float2bfloat16_rn(vv[j]);
        l[j] = __float2bfloat16_rn(vv[j] - __bfloat162float(h[j]));
    }
    *(__nv_bfloat162*)(hi + 4 * i)     = __halves2bfloat162(h[0], h[1]);
    *(__nv_bfloat162*)(hi + 4 * i + 2) = __halves2bfloat162(h[2], h[3]);
    *(__nv_bfloat162*)(lo + 4 * i)     = __halves2bfloat162(l[0], l[1]);
    *(__nv_bfloat162*)(lo + 4 * i + 2) = __halves2bfloat162(l[2], l[3]);
}

// ---------------------------------------------------------------------------
// shared PTX macros
// ---------------------------------------------------------------------------
#define CP16(dst, src) \
    asm volatile("cp.async.ca.shared.global [%0], [%1], 16;" :: "r"(dst), "l"(src))

#define LDSM4(r, addr) \
    asm volatile("ldmatrix.sync.aligned.m8n8.x4.shared.b16 {%0,%1,%2,%3}, [%4];" \
        : "=r"(r[0]), "=r"(r[1]), "=r"(r[2]), "=r"(r[3]) : "r"(addr))

#define MMA16816(d, a, b) \
    asm volatile("mma.sync.aligned.m16n8k16.row.col.f32.bf16.bf16.f32 " \
        "{%0,%1,%2,%3}, {%4,%5,%6,%7}, {%8,%9}, {%0,%1,%2,%3};" \
        : "+f"(d[0]), "+f"(d[1]), "+f"(d[2]), "+f"(d[3]) \
        : "r"(a[0]), "r"(a[1]), "r"(a[2]), "r"(a[3]), "r"(b[0]), "r"(b[1]))

#define MMA2(d, a, b0, b1) \
    asm volatile("mma.sync.aligned.m16n8k16.row.col.f32.bf16.bf16.f32 " \
        "{%0,%1,%2,%3}, {%4,%5,%6,%7}, {%8,%9}, {%0,%1,%2,%3};" \
        : "+f"(d[0]), "+f"(d[1]), "+f"(d[2]), "+f"(d[3]) \
        : "r"(a[0]), "r"(a[1]), "r"(a[2]), "r"(a[3]), "r"(b0), "r"(b1))

// ---------------------------------------------------------------------------
// bf16 3-term GEMM (unchanged from R4): out = (Ah+Al)(Bh+Bl)^T + bias
// ---------------------------------------------------------------------------
#define SM_STAGE_BYTES 40960
#define SM_B_OFF 20480

__device__ __forceinline__ void stage_load(
    unsigned sdst,
    const __nv_bfloat16* __restrict__ Ah, const __nv_bfloat16* __restrict__ Al,
    const __nv_bfloat16* __restrict__ Bh, const __nv_bfloat16* __restrict__ Bl,
    int m0, int n0, int k0, int r0, int q)
{
    const __nv_bfloat16* a = Ah + (size_t)(m0 + r0) * KDIM + k0 + q * 8;
    CP16(sdst + r0 * 80 + q * 16, a);
    CP16(sdst + (r0 + 64) * 80 + q * 16, a + 64 * KDIM);
    const __nv_bfloat16* a2 = Al + (size_t)(m0 + r0) * KDIM + k0 + q * 8;
    CP16(sdst + (r0 + 128) * 80 + q * 16, a2);
    CP16(sdst + (r0 + 192) * 80 + q * 16, a2 + 64 * KDIM);

    unsigned bdst = sdst + SM_B_OFF;
    const __nv_bfloat16* b = Bh + (size_t)(n0 + r0) * KDIM + k0 + q * 8;
    CP16(bdst + r0 * 80 + q * 16, b);
    CP16(bdst + (r0 + 64) * 80 + q * 16, b + 64 * KDIM);
    const __nv_bfloat16* b2 = Bl + (size_t)(n0 + r0) * KDIM + k0 + q * 8;
    CP16(bdst + (r0 + 128) * 80 + q * 16, b2);
    CP16(bdst + (r0 + 192) * 80 + q * 16, b2 + 64 * KDIM);
}

__device__ __forceinline__ void bf16gemm3(
    const __nv_bfloat16* __restrict__ Ah, const __nv_bfloat16* __restrict__ Al,
    const __nv_bfloat16* __restrict__ Bh, const __nv_bfloat16* __restrict__ Bl,
    const float* __restrict__ bias, float* __restrict__ out)
{
    extern __shared__ __nv_bfloat16 smem[];
    const int tid = threadIdx.x;
    const int lane = tid & 31;
    const int wid = tid >> 5;
    const int warp_m = wid & 3;
    const int warp_n = wid >> 2;
    const int m0 = blockIdx.y * 128;
    const int n0 = blockIdx.x * 128;
    const int q = tid & 3;
    const int r0 = tid >> 2;

    unsigned sbase = (unsigned)__cvta_generic_to_shared(smem);

    float acc[2][8][4];
    #pragma unroll
    for (int mt = 0; mt < 2; mt++)
        #pragma unroll
        for (int nt = 0; nt < 8; nt++)
            #pragma unroll
            for (int j = 0; j < 4; j++) acc[mt][nt][j] = 0.f;

    stage_load(sbase, Ah, Al, Bh, Bl, m0, n0, 0, r0, q);
    asm volatile("cp.async.commit_group;");

    for (int kt = 0; kt < 32; kt++) {
        if (kt < 31)
            stage_load(sbase + ((kt + 1) & 1) * SM_STAGE_BYTES,
                       Ah, Al, Bh, Bl, m0, n0, (kt + 1) * 32, r0, q);
        asm volatile("cp.async.commit_group;");
        asm volatile("cp.async.wait_group 1;");
        __syncthreads();

        unsigned base = sbase + (kt & 1) * SM_STAGE_BYTES;
        #pragma unroll
        for (int ks = 0; ks < 2; ks++) {
            unsigned lofs = (lane & 15) * 80 + (lane >> 4) * 16 + ks * 32;
            uint32_t ah[2][4], al[2][4];
            #pragma unroll
            for (int mt = 0; mt < 2; mt++) {
                unsigned ra = (warp_m * 32 + mt * 16);
                LDSM4(ah[mt], base + ra * 80 + lofs);
                LDSM4(al[mt], base + (ra + 128) * 80 + lofs);
            }
            uint32_t bh[8][2], bl[8][2];
            #pragma unroll
            for (int np = 0; np < 4; np++) {
                unsigned rb = (warp_n * 64 + np * 16);
                uint32_t t[4];
                LDSM4(t, base + SM_B_OFF + rb * 80 + lofs);
                bh[2 * np][0] = t[0]; bh[2 * np][1] = t[2];
                bh[2 * np + 1][0] = t[1]; bh[2 * np + 1][1] = t[3];
                LDSM4(t, base + SM_B_OFF + (rb + 128) * 80 + lofs);
                bl[2 * np][0] = t[0]; bl[2 * np][1] = t[2];
                bl[2 * np + 1][0] = t[1]; bl[2 * np + 1][1] = t[3];
            }
            #pragma unroll
            for (int mt = 0; mt < 2; mt++)
                #pragma unroll
                for (int nt = 0; nt < 8; nt++) {
                    MMA16816(acc[mt][nt], ah[mt], bh[nt]);
                    MMA16816(acc[mt][nt], ah[mt], bl[nt]);
                    MMA16816(acc[mt][nt], al[mt], bh[nt]);
                }
        }
        __syncthreads();
    }

    #pragma unroll
    for (int mt = 0; mt < 2; mt++) {
        int m = m0 + warp_m * 32 + mt * 16 + (lane >> 2);
        #pragma unroll
        for (int nt = 0; nt < 8; nt++) {
            int n = n0 + warp_n * 64 + nt * 8 + 2 * (lane & 3);
            float2 b2 = *(const float2*)(bias + n);
            float2 v0 = make_float2(acc[mt][nt][0] + b2.x, acc[mt][nt][1] + b2.y);
            float2 v1 = make_float2(acc[mt][nt][2] + b2.x, acc[mt][nt][3] + b2.y);
            *(float2*)(out + (size_t)m * C_ + n) = v0;
            *(float2*)(out + (size_t)(m + 8) * C_ + n) = v1;
        }
    }
}

__global__ void __launch_bounds__(256) qkv_kernel(
    const float* __restrict__ bq, const float* __restrict__ bk,
    const float* __restrict__ bv)
{
    int z = blockIdx.z;
    const float* bias = (z == 0) ? bq : (z == 1) ? bk : bv;
    float* out = (z == 0) ? g_q : (z == 1) ? g_k : g_v;
    bf16gemm3(g_xh, g_xl, g_wh + (size_t)z * C_ * C_, g_wl + (size_t)z * C_ * C_,
              bias, out);
}

__global__ void __launch_bounds__(256) oproj_kernel(
    const float* __restrict__ bo, float* __restrict__ out)
{
    bf16gemm3(g_ah, g_al, g_wh + (size_t)3 * C_ * C_, g_wl + (size_t)3 * C_ * C_,
              bo, out);
}

// ---------------------------------------------------------------------------
// helpers for bf16 packing
// ---------------------------------------------------------------------------
__device__ __forceinline__ uint32_t packbf(float lo, float hi) {
    uint32_t r;
    asm("cvt.rn.bf16x2.f32 %0, %1, %2;" : "=r"(r) : "f"(hi), "f"(lo));
    return r;
}
__device__ __forceinline__ float bflo(uint32_t u) { return __int_as_float(u << 16); }
__device__ __forceinline__ float bfhi(uint32_t u) { return __int_as_float(u & 0xffff0000u); }

// exp2 on the FMA pipe (avoids the 0.96ms MUFU floor); rel err ~3e-8
__device__ __forceinline__ float fast_exp2(float x) {
    x = fmaxf(x, -126.f);
    int e = __float2int_rn(x);
    float f = x - (float)e;                       // [-0.5, 0.5]
    float p = 1.5403530393e-4f;
    p = fmaf(p, f, 1.3333558146e-3f);
    p = fmaf(p, f, 9.6181291076e-3f);
    p = fmaf(p, f, 5.5504108664e-2f);
    p = fmaf(p, f, 2.4022650696e-1f);
    p = fmaf(p, f, 6.9314718056e-1f);
    p = fmaf(p, f, 1.0f);
    return __int_as_float((e + 127) << 23) * p;
}

// ---------------------------------------------------------------------------
// RoPE + split: read g_q/g_k fp32, apply rope, write bf16 hi/lo.
// Q additionally scaled by 0.125*log2(e) so softmax uses exp2.
// ---------------------------------------------------------------------------
#define SCALE_Q 0.18033688011112042f   // 0.125 * log2(e)

__global__ void __launch_bounds__(256) rope_split_kernel()
{
    __shared__ float invf[32];
    if (threadIdx.x < 32) {
        invf[threadIdx.x] =
            (float)exp(-(double)threadIdx.x * 0.28782313662425560116456546736598);
    }
    __syncthreads();

    int idx = blockIdx.x * blockDim.x + threadIdx.x;
    if (idx >= B_ * T_ * (C_ / 2)) return;
    int p  = idx & (C_ / 2 - 1);
    int bt = idx >> 9;
    int t  = bt & (T_ - 1);
    int c  = p * 2;
    int d0 = c & (D_ - 1);

    float a0 = (float)t * invf[d0 & 31];
    float a1 = (float)t * invf[(d0 + 1) & 31];
    float s0, c0, s1, c1;
    sincosf(a0, &s0, &c0);
    sincosf(a1, &s1, &c1);

    size_t off = (size_t)bt * C_ + c;
    float2 qv = *(float2*)(g_q + off);
    float2 kv = *(float2*)(g_k + off);
    float q0 = (qv.x * c0 - qv.y * s0) * SCALE_Q;
    float q1 = (qv.y * c1 + qv.x * s1) * SCALE_Q;
    float k0 = kv.x * c0 - kv.y * s0;
    float k1 = kv.y * c1 + kv.x * s1;

    uint32_t qh = packbf(q0, q1);
    uint32_t ql = packbf(q0 - bflo(qh), q1 - bfhi(qh));
    uint32_t kh = packbf(k0, k1);
    uint32_t kl = packbf(k0 - bflo(kh), k1 - bfhi(kh));
    *(uint32_t*)(g_qh + off) = qh;
    *(uint32_t*)(g_ql + off) = ql;
    *(uint32_t*)(g_kh + off) = kh;
    *(uint32_t*)(g_kl + off) = kl;
}

// ---------------------------------------------------------------------------
// V transpose + split: g_v [b][t][h*64+d] fp32 -> g_vth/g_vtl [(b*16+h)*64+d][t]
// ---------------------------------------------------------------------------
__global__ void __launch_bounds__(256) vt_split_kernel()
{
    __shared__ float tile[32][33];
    int bh = blockIdx.z;
    int b = bh >> 4, h = bh & 15;
    int t0 = blockIdx.x * 32;
    int d0 = blockIdx.y * 32;
    int tx = threadIdx.x, ty = threadIdx.y;

    #pragma unroll
    for (int i = 0; i < 4; i++) {
        int t = t0 + ty + i * 8;
        tile[ty + i * 8][tx] = g_v[(size_t)(b * T_ + t) * C_ + h * D_ + d0 + tx];
    }
    __syncthreads();
    #pragma unroll
    for (int i = 0; i < 4; i++) {
        int d = d0 + ty + i * 8;
        float v = tile[tx][ty + i * 8];
        __nv_bfloat16 vh = __float2bfloat16_rn(v);
        __nv_bfloat16 vl = __float2bfloat16_rn(v - __bfloat162float(vh));
        size_t o = (size_t)(bh * D_ + d) * T_ + t0 + tx;
        g_vth[o] = vh;
        g_vtl[o] = vl;
    }
}

// ---------------------------------------------------------------------------
// Tensor-core flash attention.
// CTA: 64 q-rows of one (b,h); 128 threads = 4 warps, 16 rows/warp.
// Key tiles Bc=64, double-buffered cp.async. All matmuls bf16 3-term mma.
// Smem pitch 72 bf16 (144B) rows -> conflict-free ldmatrix.
// ---------------------------------------------------------------------------
#define FP 144                       // row pitch bytes
#define QTILE 9216                   // 64*144
#define SKBUF 18432                  // Kh+Kl per stage
#define FLASH_SMEM (18432 + 2*18432 + 2*18432)   // Q + K*2 + V*2 = 92160

__device__ __forceinline__ void flash_stage_kv(
    unsigned kbuf, unsigned vbuf, int b, int h, int bh, int kt, int tid)
{
    #pragma unroll
    for (int i = 0; i < 4; i++) {
        int idx = tid + i * 128;        // 0..511
        int r = idx >> 3, c = idx & 7;
        const __nv_bfloat16* kh = g_kh + (size_t)(b * T_ + kt * 64 + r) * C_ + h * D_ + c * 8;
        const __nv_bfloat16* kl = g_kl + (size_t)(b * T_ + kt * 64 + r) * C_ + h * D_ + c * 8;
        CP16(kbuf + r * FP + c * 16, kh);
        CP16(kbuf + QTILE + r * FP + c * 16, kl);
        const __nv_bfloat16* vh = g_vth + (size_t)(bh * D_ + r) * T_ + kt * 64 + c * 8;
        const __nv_bfloat16* vl = g_vtl + (size_t)(bh * D_ + r) * T_ + kt * 64 + c * 8;
        CP16(vbuf + r * FP + c * 16, vh);
        CP16(vbuf + QTILE + r * FP + c * 16, vl);
    }
}

__global__ void __launch_bounds__(128) flash_tc_kernel()
{
    extern __shared__ char fsm[];
    const unsigned sb = (unsigned)__cvta_generic_to_shared(fsm);
    const unsigned sQH = sb;                    // +QTILE = sQL
    const unsigned sK0 = sb + 18432;            // stage s at +s*SKBUF; lo at +QTILE
    const unsigned sV0 = sb + 18432 + 2 * SKBUF;

    const int tid = threadIdx.x;
    const int lane = tid & 31;
    const int w = tid >> 5;
    const int bh = blockIdx.y;
    const int b = bh >> 4, h = bh & 15;
    const int t0 = blockIdx.x * 64;

    // stage Q (hi+lo) and K/V tile 0
    #pragma unroll
    for (int i = 0; i < 4; i++) {
        int idx = tid + i * 128;
        int r = idx >> 3, c = idx & 7;
        const __nv_bfloat16* qh = g_qh + (size_t)(b * T_ + t0 + r) * C_ + h * D_ + c * 8;
        const __nv_bfloat16* ql = g_ql + (size_t)(b * T_ + t0 + r) * C_ + h * D_ + c * 8;
        CP16(sQH + r * FP + c * 16, qh);
        CP16(sQH + QTILE + r * FP + c * 16, ql);
    }
    flash_stage_kv(sK0, sV0, b, h, bh, 0, tid);
    asm volatile("cp.async.commit_group;");
    asm volatile("cp.async.wait_group 0;");
    __syncthreads();

    // load Q fragments (persistent)
    uint32_t qh[4][4], ql[4][4];
    {
        int m = lane >> 3;
        int rofs = (lane & 7) + ((m & 1) ? 8 : 0);
        int cbase = (m >> 1) ? 16 : 0;
        #pragma unroll
        for (int ks = 0; ks < 4; ks++) {
            unsigned a = sQH + (16 * w + rofs) * FP + ks * 32 + cbase;
            LDSM4(qh[ks], a);
            LDSM4(ql[ks], (a + QTILE));
        }
    }

    float m0 = -1e30f, m1 = -1e30f, l0 = 0.f, l1 = 0.f;
    float o[8][4];
    #pragma unroll
    for (int nt = 0; nt < 8; nt++)
        #pragma unroll
        for (int j = 0; j < 4; j++) o[nt][j] = 0.f;

    // K/V fragment lane addressing (same for K and V)
    const int fm = lane >> 3;
    const int frofs = (lane & 7) + ((fm >> 1) ? 8 : 0);
    const int fcofs = (fm & 1) ? 16 : 0;

    for (int kt = 0; kt < T_ / 64; kt++) {
        if (kt < T_ / 64 - 1)
            flash_stage_kv(sK0 + ((kt + 1) & 1) * SKBUF, sV0 + ((kt + 1) & 1) * SKBUF,
                           b, h, bh, kt + 1, tid);
        asm volatile("cp.async.commit_group;");
        asm volatile("cp.async.wait_group 1;");
        __syncthreads();

        const unsigned kb = sK0 + (kt & 1) * SKBUF;
        const unsigned vb = sV0 + (kt & 1) * SKBUF;

        // ---- S = Q K^T (3-term) ----
        float s[8][4];
        #pragma unroll
        for (int nt = 0; nt < 8; nt++)
            #pragma unroll
            for (int j = 0; j < 4; j++) s[nt][j] = 0.f;

        #pragma unroll
        for (int ks = 0; ks < 4; ks++) {
            uint32_t kfh[4][4], kfl[4][4];
            #pragma unroll
            for (int j = 0; j < 4; j++) {
                unsigned a = kb + (16 * j + frofs) * FP + ks * 32 + fcofs;
                LDSM4(kfh[j], a);
                LDSM4(kfl[j], (a + QTILE));
            }
            #pragma unroll
            for (int j = 0; j < 4; j++) {
                MMA2(s[2 * j],     qh[ks], kfh[j][0], kfh[j][1]);
                MMA2(s[2 * j],     qh[ks], kfl[j][0], kfl[j][1]);
                MMA2(s[2 * j],     ql[ks], kfh[j][0], kfh[j][1]);
                MMA2(s[2 * j + 1], qh[ks], kfh[j][2], kfh[j][3]);
                MMA2(s[2 * j + 1], qh[ks], kfl[j][2], kfl[j][3]);
                MMA2(s[2 * j + 1], ql[ks], kfh[j][2], kfh[j][3]);
            }
        }

        // ---- online softmax (rows g=lane>>2 and g+8) ----
        float mx0 = -1e30f, mx1 = -1e30f;
        #pragma unroll
        for (int nt = 0; nt < 8; nt++) {
            mx0 = fmaxf(mx0, fmaxf(s[nt][0], s[nt][1]));
            mx1 = fmaxf(mx1, fmaxf(s[nt][2], s[nt][3]));
        }
        mx0 = fmaxf(mx0, __shfl_xor_sync(0xffffffffu, mx0, 1));
        mx0 = fmaxf(mx0, __shfl_xor_sync(0xffffffffu, mx0, 2));
        mx1 = fmaxf(mx1, __shfl_xor_sync(0xffffffffu, mx1, 1));
        mx1 = fmaxf(mx1, __shfl_xor_sync(0xffffffffu, mx1, 2));
        float mn0 = fmaxf(m0, mx0), mn1 = fmaxf(m1, mx1);
        float sc0 = fast_exp2(m0 - mn0), sc1 = fast_exp2(m1 - mn1);
        m0 = mn0; m1 = mn1;

        float rs0 = 0.f, rs1 = 0.f;
        #pragma unroll
        for (int nt = 0; nt < 8; nt++) {
            s[nt][0] = fast_exp2(s[nt][0] - mn0);
            s[nt][1] = fast_exp2(s[nt][1] - mn0);
            s[nt][2] = fast_exp2(s[nt][2] - mn1);
            s[nt][3] = fast_exp2(s[nt][3] - mn1);
            rs0 += s[nt][0] + s[nt][1];
            rs1 += s[nt][2] + s[nt][3];
        }
        rs0 += __shfl_xor_sync(0xffffffffu, rs0, 1);
        rs0 += __shfl_xor_sync(0xffffffffu, rs0, 2);
        rs1 += __shfl_xor_sync(0xffffffffu, rs1, 1);
        rs1 += __shfl_xor_sync(0xffffffffu, rs1, 2);
        l0 = l0 * sc0 + rs0;
        l1 = l1 * sc1 + rs1;

        #pragma unroll
        for (int nt = 0; nt < 8; nt++) {
            o[nt][0] *= sc0; o[nt][1] *= sc0;
            o[nt][2] *= sc1; o[nt][3] *= sc1;
        }

        // ---- pack P into A-fragments (hi + lo) ----
        uint32_t aph[4][4], apl[4][4];
        #pragma unroll
        for (int ks = 0; ks < 4; ks++) {
            float* p0 = s[2 * ks];
            float* p1 = s[2 * ks + 1];
            uint32_t h0 = packbf(p0[0], p0[1]);
            uint32_t h1 = packbf(p0[2], p0[3]);
            uint32_t h2 = packbf(p1[0], p1[1]);
            uint32_t h3 = packbf(p1[2], p1[3]);
            aph[ks][0] = h0; aph[ks][1] = h1; aph[ks][2] = h2; aph[ks][3] = h3;
            apl[ks][0] = packbf(p0[0] - bflo(h0), p0[1] - bfhi(h0));
            apl[ks][1] = packbf(p0[2] - bflo(h1), p0[3] - bfhi(h1));
            apl[ks][2] = packbf(p1[0] - bflo(h2), p1[1] - bfhi(h2));
            apl[ks][3] = packbf(p1[2] - bflo(h3), p1[3] - bfhi(h3));
        }

        // ---- O += P V (3-term) ----
        #pragma unroll
        for (int ks = 0; ks < 4; ks++) {
            uint32_t vfh[4][4], vfl[4][4];
            #pragma unroll
            for (int j = 0; j < 4; j++) {
                unsigned a = vb + (16 * j + frofs) * FP + ks * 32 + fcofs;
                LDSM4(vfh[j], a);
                LDSM4(vfl[j], (a + QTILE));
            }
            #pragma unroll
            for (int j = 0; j < 4; j++) {
                MMA2(o[2 * j],     aph[ks], vfh[j][0], vfh[j][1]);
                MMA2(o[2 * j],     aph[ks], vfl[j][0], vfl[j][1]);
                MMA2(o[2 * j],     apl[ks], vfh[j][0], vfh[j][1]);
                MMA2(o[2 * j + 1], aph[ks], vfh[j][2], vfh[j][3]);
                MMA2(o[2 * j + 1], aph[ks], vfl[j][2], vfl[j][3]);
                MMA2(o[2 * j + 1], apl[ks], vfh[j][2], vfh[j][3]);
            }
        }
        __syncthreads();
    }

    // ---- epilogue: normalize, split hi/lo, write g_ah/g_al ----
    float inv0 = 1.0f / l0, inv1 = 1.0f / l1;
    size_t row0 = (size_t)(b * T_ + t0 + 16 * w + (lane >> 2)) * C_ + h * D_;
    int colb = 2 * (lane & 3);
    #pragma unroll
    for (int nt = 0; nt < 8; nt++) {
        float v0 = o[nt][0] * inv0, v1 = o[nt][1] * inv0;
        uint32_t hp = packbf(v0, v1);
        uint32_t lp = packbf(v0 - bflo(hp), v1 - bfhi(hp));
        *(uint32_t*)(g_ah + row0 + nt * 8 + colb) = hp;
        *(uint32_t*)(g_al + row0 + nt * 8 + colb) = lp;
        float v2 = o[nt][2] * inv1, v3 = o[nt][3] * inv1;
        uint32_t hp2 = packbf(v2, v3);
        uint32_t lp2 = packbf(v2 - bflo(hp2), v3 - bfhi(hp2));
        *(uint32_t*)(g_ah + row0 + 8 * C_ + nt * 8 + colb) = hp2;
        *(uint32_t*)(g_al + row0 + 8 * C_ + nt * 8 + colb) = lp2;
    }
}

// ---------------------------------------------------------------------------
extern "C" void kernel_launch(void* const* d_in, const int* in_sizes, int n_in,
                              void* d_out, int out_size)
{
    const float* x  = (const float*)d_in[0];
    const float* wq = (const float*)d_in[1];
    const float* bq = (const float*)d_in[2];
    const float* wk = (const float*)d_in[3];
    const float* bk = (const float*)d_in[4];
    const float* wv = (const float*)d_in[5];
    const float* bv = (const float*)d_in[6];
    const float* wo = (const float*)d_in[7];
    const float* bo = (const float*)d_in[8];
    float* out = (float*)d_out;

    __nv_bfloat16 *xh, *xl, *wh, *wl;
    cudaGetSymbolAddress((void**)&xh, g_xh);
    cudaGetSymbolAddress((void**)&xl, g_xl);
    cudaGetSymbolAddress((void**)&wh, g_wh);
    cudaGetSymbolAddress((void**)&wl, g_wl);

    // Split x and weights into bf16 hi/lo
    split_kernel<<<(NELEM / 4 + 255) / 256, 256>>>(x, xh, xl, NELEM / 4);
    int wn4 = C_ * C_ / 4;
    split_kernel<<<(wn4 + 255) / 256, 256>>>(wq, wh + 0 * C_ * C_, wl + 0 * C_ * C_, wn4);
    split_kernel<<<(wn4 + 255) / 256, 256>>>(wk, wh + 1 * C_ * C_, wl + 1 * C_ * C_, wn4);
    split_kernel<<<(wn4 + 255) / 256, 256>>>(wv, wh + 2 * C_ * C_, wl + 2 * C_ * C_, wn4);
    split_kernel<<<(wn4 + 255) / 256, 256>>>(wo, wh + 3 * C_ * C_, wl + 3 * C_ * C_, wn4);

    // QKV projections (bf16x3 tensor core)
    cudaFuncSetAttribute(qkv_kernel,
                         cudaFuncAttributeMaxDynamicSharedMemorySize, 2 * SM_STAGE_BYTES);
    cudaFuncSetAttribute(oproj_kernel,
                         cudaFuncAttributeMaxDynamicSharedMemorySize, 2 * SM_STAGE_BYTES);
    qkv_kernel<<<dim3(C_ / 128, M_ / 128, 3), 256, 2 * SM_STAGE_BYTES>>>(bq, bk, bv);

    // RoPE + Q/K hi-lo split
    int npairs = B_ * T_ * (C_ / 2);
    rope_split_kernel<<<(npairs + 255) / 256, 256>>>();

    // V transpose + split
    vt_split_kernel<<<dim3(T_ / 32, D_ / 32, B_ * H_), dim3(32, 8)>>>();

    // Tensor-core flash attention
    cudaFuncSetAttribute(flash_tc_kernel,
                         cudaFuncAttributeMaxDynamicSharedMemorySize, FLASH_SMEM);
    flash_tc_kernel<<<dim3(T_ / 64, B_ * H_), 128, FLASH_SMEM>>>();

    // Output projection
    oproj_kernel<<<dim3(C_ / 128, M_ / 128), 256, 2 * SM_STAGE_BYTES>>>(bo, out);
}